// round 15
// baseline (speedup 1.0000x reference)
#include <cuda_runtime.h>
#include <cuda_bf16.h>

// IIR filterbank: x (128, 4, 65536) f32, b/a (4, 5) f32, out same shape.
// Direct-form-II-transposed per (batch, filter) sequence.
//
// Overlap-save chunking (repeated poles at radius 0.9; truncation error
// ~n^3*0.9^n -> WARM=256 gives ~3e-5, fixed) + smem transpose staging +
// register-file prefetch (no cp.async — hangs this harness).
//
// R15: CHUNK=256. Doubles thread count (131072) -> grid=1024 at TPB=128:
//   wave efficiency 98.8% (vs 86.5% at grid 512), ~6 blocks/SM resident.
//   Warm re-reads (now 2x) are L2 hits (L2 was 34% busy), so DRAM bytes
//   stay at the unique footprint. Blocks stay 4 warps (R14 showed 2-warp
//   blocks regress).
//
//   block = half sequence (128 chunks of 256); 16 lockstep tiles of 32
//   samples/thread (8 warm-up + 8 main).
//   smem: 2 static buffers of 128 x PITCH(36) floats = 36,864 B.

#define T_LEN   65536
#define CHUNK   256
#define WARM    256
#define TPB     128                    // chunks per block
#define TT      32
#define NT_WARM (WARM / TT)            // 8
#define NT      ((WARM + CHUNK) / TT)  // 16
#define PITCH   36                     // floats; conflict-free LDS.128 phases
#define BUF_FLOATS (TPB * PITCH)       // 4608
#define CHUNKS_PER_SEQ (T_LEN / CHUNK) // 256

__global__ __launch_bounds__(TPB)
void iir_c256_kernel(const float* __restrict__ x,
                     const float* __restrict__ bc,
                     const float* __restrict__ ac,
                     float* __restrict__ out)
{
    __shared__ float sbuf[2][BUF_FLOATS];

    const int seq   = blockIdx.x >> 1;         // 0..511, (batch, filter, T)
    const int half  = blockIdx.x & 1;
    const int tid   = threadIdx.x;
    const int filt  = seq & 3;
    const int cbase = half * TPB;              // first chunk-in-seq for this block

    const float inv = 1.0f / ac[filt * 5 + 0];
    const float b0 = bc[filt * 5 + 0] * inv;
    const float b1 = bc[filt * 5 + 1] * inv;
    const float b2 = bc[filt * 5 + 2] * inv;
    const float b3 = bc[filt * 5 + 3] * inv;
    const float b4 = bc[filt * 5 + 4] * inv;
    const float na1 = -ac[filt * 5 + 1] * inv;
    const float na2 = -ac[filt * 5 + 2] * inv;
    const float na3 = -ac[filt * 5 + 3] * inv;
    const float na4 = -ac[filt * 5 + 4] * inv;

    const float* xs = x   + (size_t)seq * T_LEN;
    float*       ys = out + (size_t)seq * T_LEN;

    // Cooperative tile: 128 rows x 32 floats = 1024 float4, 8 per thread.
    // Slot q: row = q>>3, c4 = q&7. Row r -> chunk (cbase + r).
    // Gmem position, tile j: (cbase+r)*CHUNK - WARM + j*TT + c4*4.

    float4 pf[8];   // prefetched tile held in registers

    // ---- load tile 0 (coalesced LDG.128) ----
    #pragma unroll
    for (int i = 0; i < 8; i++) {
        const int q   = i * TPB + tid;
        const int row = q >> 3;
        const int c4  = q & 7;
        const int p   = (cbase + row) * CHUNK - WARM + c4 * 4;   // j = 0
        pf[i] = (p >= 0) ? *reinterpret_cast<const float4*>(xs + p)
                         : make_float4(0.f, 0.f, 0.f, 0.f);
    }

    float z0 = 0.f, z1 = 0.f, z2 = 0.f, z3 = 0.f;

    for (int j = 0; j < NT; j++) {
        float* buf = sbuf[j & 1];

        // ---- stage prefetched registers into smem (coalesced STS.128) ----
        #pragma unroll
        for (int i = 0; i < 8; i++) {
            const int q   = i * TPB + tid;
            const int row = q >> 3;
            const int c4  = q & 7;
            *reinterpret_cast<float4*>(buf + row * PITCH + c4 * 4) = pf[i];
        }
        __syncthreads();

        // ---- issue next tile's LDGs now; consumed next iteration ----
        if (j + 1 < NT) {
            #pragma unroll
            for (int i = 0; i < 8; i++) {
                const int q   = i * TPB + tid;
                const int row = q >> 3;
                const int c4  = q & 7;
                const int p   = (cbase + row) * CHUNK - WARM + (j + 1) * TT + c4 * 4;
                pf[i] = (p >= 0) ? *reinterpret_cast<const float4*>(xs + p)
                                 : make_float4(0.f, 0.f, 0.f, 0.f);
            }
        }

        // ---- serial recurrence over own smem row, outputs in place ----
        float* row = buf + tid * PITCH;
        const bool mainTile = (j >= NT_WARM);
        #pragma unroll
        for (int i = 0; i < 8; i++) {
            const float4 xv = *reinterpret_cast<const float4*>(row + i * 4);
            const float xa[4] = {xv.x, xv.y, xv.z, xv.w};
            float yv[4];
            #pragma unroll
            for (int k = 0; k < 4; k++) {
                const float xn = xa[k];
                const float y   = fmaf(b0, xn, z0);
                const float nz0 = fmaf(na1, y, fmaf(b1, xn, z1));
                const float nz1 = fmaf(na2, y, fmaf(b2, xn, z2));
                const float nz2 = fmaf(na3, y, fmaf(b3, xn, z3));
                const float nz3 = fmaf(na4, y, b4 * xn);
                z0 = nz0; z1 = nz1; z2 = nz2; z3 = nz3;
                yv[k] = y;
            }
            if (mainTile)
                *reinterpret_cast<float4*>(row + i * 4) =
                    make_float4(yv[0], yv[1], yv[2], yv[3]);
        }
        __syncthreads();

        // ---- cooperative coalesced store of main-tile outputs ----
        if (mainTile) {
            const int tbase = (j - NT_WARM) * TT;
            #pragma unroll
            for (int i = 0; i < 8; i++) {
                const int q   = i * TPB + tid;
                const int r   = q >> 3;
                const int c4  = q & 7;
                *reinterpret_cast<float4*>(ys + (cbase + r) * CHUNK + tbase + c4 * 4) =
                    *reinterpret_cast<const float4*>(buf + r * PITCH + c4 * 4);
            }
        }
    }
}

extern "C" void kernel_launch(void* const* d_in, const int* in_sizes, int n_in,
                              void* d_out, int out_size)
{
    const float* x  = (const float*)d_in[0];   // (128, 4, 65536)
    const float* bc = (const float*)d_in[1];   // (4, 5)
    const float* ac = (const float*)d_in[2];   // (4, 5)
    float* out = (float*)d_out;

    iir_c256_kernel<<<1024, TPB>>>(x, bc, ac, out);
}

// round 16
// speedup vs baseline: 1.5204x; 1.5204x over previous
#include <cuda_runtime.h>
#include <cuda_bf16.h>

// IIR filterbank: x (128, 4, 65536) f32, b/a (4, 5) f32, out same shape.
// Direct-form-II-transposed per (batch, filter) sequence.
//
// Overlap-save chunking (repeated poles at radius 0.9; truncation error
// ~n^3*0.9^n -> WARM=256 gives ~3e-5) + smem transpose staging + register-
// file prefetch (no cp.async — hangs this harness). R13 structure kept.
//
// R16: per-SM load balancing. 65536 chunk-rows are distributed over
// grid=592 (=4*148) blocks of 111 rows each (last blocks tail-guarded),
// so every SM hosts exactly 4 equal blocks: makespan 4*111=444 row-units
// vs R13's worst-SM 4*128=512 (512 blocks split 4-vs-3 across 148 SMs).
//
//   Each thread (tid<111) owns one 512-sample chunk; 24 lockstep tiles of
//   32 samples (8 warm-up + 16 main). smem 2 x 111 x 36 floats = 31,968 B.

#define T_LEN   65536
#define CHUNK   512
#define WARM    256
#define TPB     128
#define ROWS    111                    // chunk-rows per block
#define GRID    592                    // 4 * 148
#define TT      32
#define NT_WARM (WARM / TT)            // 8
#define NT      ((WARM + CHUNK) / TT)  // 24
#define PITCH   36                     // floats; conflict-free LDS.128 phases
#define BUF_FLOATS (ROWS * PITCH)      // 3996
#define N4      (ROWS * 8)             // float4 slots per tile = 888
#define NROWS_TOTAL 65536              // 512 seq * 128 chunks

__global__ __launch_bounds__(TPB)
void iir_bal_kernel(const float* __restrict__ x,
                    const float* __restrict__ bc,
                    const float* __restrict__ ac,
                    float* __restrict__ out)
{
    __shared__ float sbuf[2][BUF_FLOATS];

    const int tid   = threadIdx.x;
    const int rbase = blockIdx.x * ROWS;       // first global chunk-row

    // This thread's own row (compute role).
    const int my_rg   = rbase + tid;
    const bool active = (tid < ROWS) && (my_rg < NROWS_TOTAL);
    const int filt    = (my_rg >> 7) & 3;      // seq = rg>>7, filt = seq&3

    const float inv = 1.0f / ac[filt * 5 + 0];
    const float b0 = bc[filt * 5 + 0] * inv;
    const float b1 = bc[filt * 5 + 1] * inv;
    const float b2 = bc[filt * 5 + 2] * inv;
    const float b3 = bc[filt * 5 + 3] * inv;
    const float b4 = bc[filt * 5 + 4] * inv;
    const float na1 = -ac[filt * 5 + 1] * inv;
    const float na2 = -ac[filt * 5 + 2] * inv;
    const float na3 = -ac[filt * 5 + 3] * inv;
    const float na4 = -ac[filt * 5 + 4] * inv;

    // Cooperative tile layout: slot q in [0, N4): row = q>>3, c4 = q&7.
    // Global chunk-row rg = rbase + row; sequence-local chunk = rg & 127.
    // Gmem sample index for tile j, slot q:
    //   seq_base = (rg>>7)*65536;  p_seq = (rg&127)*512 - WARM + j*TT + c4*4
    //   load iff rg < 65536 && p_seq >= 0.

    float4 pf[7];   // prefetched tile in registers (7*128 = 896 >= 888 slots)

    // ---- load tile 0 (coalesced LDG.128) ----
    #pragma unroll
    for (int i = 0; i < 7; i++) {
        const int q = i * TPB + tid;
        float4 v = make_float4(0.f, 0.f, 0.f, 0.f);
        if (q < N4) {
            const int row = q >> 3;
            const int c4  = q & 7;
            const int rg  = rbase + row;
            const int ps  = (rg & 127) * CHUNK - WARM + c4 * 4;   // j = 0
            if (rg < NROWS_TOTAL && ps >= 0)
                v = *reinterpret_cast<const float4*>(
                        x + (size_t)(rg >> 7) * T_LEN + ps);
        }
        pf[i] = v;
    }

    float z0 = 0.f, z1 = 0.f, z2 = 0.f, z3 = 0.f;

    for (int j = 0; j < NT; j++) {
        float* buf = sbuf[j & 1];

        // ---- stage prefetched registers into smem (coalesced STS.128) ----
        #pragma unroll
        for (int i = 0; i < 7; i++) {
            const int q = i * TPB + tid;
            if (q < N4) {
                const int row = q >> 3;
                const int c4  = q & 7;
                *reinterpret_cast<float4*>(buf + row * PITCH + c4 * 4) = pf[i];
            }
        }
        __syncthreads();

        // ---- issue next tile's LDGs now; consumed next iteration ----
        if (j + 1 < NT) {
            #pragma unroll
            for (int i = 0; i < 7; i++) {
                const int q = i * TPB + tid;
                float4 v = make_float4(0.f, 0.f, 0.f, 0.f);
                if (q < N4) {
                    const int row = q >> 3;
                    const int c4  = q & 7;
                    const int rg  = rbase + row;
                    const int ps  = (rg & 127) * CHUNK - WARM + (j + 1) * TT + c4 * 4;
                    if (rg < NROWS_TOTAL && ps >= 0)
                        v = *reinterpret_cast<const float4*>(
                                x + (size_t)(rg >> 7) * T_LEN + ps);
                }
                pf[i] = v;
            }
        }

        // ---- serial recurrence over own smem row, outputs in place ----
        const bool mainTile = (j >= NT_WARM);
        if (active) {
            float* row = buf + tid * PITCH;
            #pragma unroll
            for (int i = 0; i < 8; i++) {
                const float4 xv = *reinterpret_cast<const float4*>(row + i * 4);
                const float xa[4] = {xv.x, xv.y, xv.z, xv.w};
                float yv[4];
                #pragma unroll
                for (int k = 0; k < 4; k++) {
                    const float xn = xa[k];
                    const float y   = fmaf(b0, xn, z0);
                    const float nz0 = fmaf(na1, y, fmaf(b1, xn, z1));
                    const float nz1 = fmaf(na2, y, fmaf(b2, xn, z2));
                    const float nz2 = fmaf(na3, y, fmaf(b3, xn, z3));
                    const float nz3 = fmaf(na4, y, b4 * xn);
                    z0 = nz0; z1 = nz1; z2 = nz2; z3 = nz3;
                    yv[k] = y;
                }
                if (mainTile)
                    *reinterpret_cast<float4*>(row + i * 4) =
                        make_float4(yv[0], yv[1], yv[2], yv[3]);
            }
        }
        __syncthreads();

        // ---- cooperative coalesced store of main-tile outputs ----
        if (mainTile) {
            const int tbase = (j - NT_WARM) * TT;
            #pragma unroll
            for (int i = 0; i < 7; i++) {
                const int q = i * TPB + tid;
                if (q < N4) {
                    const int row = q >> 3;
                    const int c4  = q & 7;
                    const int rg  = rbase + row;
                    if (rg < NROWS_TOTAL)
                        *reinterpret_cast<float4*>(
                            out + (size_t)rg * CHUNK + tbase + c4 * 4) =
                            *reinterpret_cast<const float4*>(buf + row * PITCH + c4 * 4);
                }
            }
        }
    }
}

extern "C" void kernel_launch(void* const* d_in, const int* in_sizes, int n_in,
                              void* d_out, int out_size)
{
    const float* x  = (const float*)d_in[0];   // (128, 4, 65536)
    const float* bc = (const float*)d_in[1];   // (4, 5)
    const float* ac = (const float*)d_in[2];   // (4, 5)
    float* out = (float*)d_out;

    iir_bal_kernel<<<GRID, TPB>>>(x, bc, ac, out);
}

// round 17
// speedup vs baseline: 1.5658x; 1.0299x over previous
#include <cuda_runtime.h>
#include <cuda_bf16.h>

// IIR filterbank: x (128, 4, 65536) f32, b/a (4, 5) f32, out same shape.
// Direct-form-II-transposed per (batch, filter) sequence.
//
// Overlap-save chunking (repeated poles at radius 0.9; WARM=256 -> ~3e-5)
// + smem transpose staging + register-file prefetch (no cp.async) + per-SM
// balanced grid 592 = 4*148 blocks of 111 chunk-rows (R16).
//
// R17: strength-reduced addressing. Because WARM == 8 tiles, tile-j store
// offset == tile-j load offset, so each cooperative slot keeps ONE running
// int offset (advanced 32/tile) plus two precomputed mask bits:
//   inb  : global row in range (and slot < 888)
//   wok  : inb && row is not chunk 0 of its sequence (p>=0 for warm loads)
// Warm-load masking (tiles 0..7) is a uniform branch on j. Next-tile LDGs
// issue BEFORE the post-STS barrier (no smem dependence).

#define T_LEN   65536
#define CHUNK   512
#define WARM    256
#define TPB     128
#define ROWS    111                    // chunk-rows per block
#define GRID    592                    // 4 * 148
#define TT      32
#define NT_WARM (WARM / TT)            // 8
#define NT      ((WARM + CHUNK) / TT)  // 24
#define PITCH   36                     // floats; conflict-free LDS.128 phases
#define BUF_FLOATS (ROWS * PITCH)      // 3996
#define N4      (ROWS * 8)             // float4 slots per tile = 888
#define NROWS_TOTAL 65536

__global__ __launch_bounds__(TPB)
void iir_sr_kernel(const float* __restrict__ x,
                   const float* __restrict__ bc,
                   const float* __restrict__ ac,
                   float* __restrict__ out)
{
    __shared__ float sbuf[2][BUF_FLOATS];

    const int tid   = threadIdx.x;
    const int rbase = blockIdx.x * ROWS;

    // ---- compute-role setup ----
    const int  my_rg  = rbase + tid;
    const bool active = (tid < ROWS) && (my_rg < NROWS_TOTAL);
    const int  filt   = (my_rg >> 7) & 3;

    const float inv = 1.0f / ac[filt * 5 + 0];
    const float b0 = bc[filt * 5 + 0] * inv;
    const float b1 = bc[filt * 5 + 1] * inv;
    const float b2 = bc[filt * 5 + 2] * inv;
    const float b3 = bc[filt * 5 + 3] * inv;
    const float b4 = bc[filt * 5 + 4] * inv;
    const float na1 = -ac[filt * 5 + 1] * inv;
    const float na2 = -ac[filt * 5 + 2] * inv;
    const float na3 = -ac[filt * 5 + 3] * inv;
    const float na4 = -ac[filt * 5 + 4] * inv;

    // ---- cooperative-slot setup (7 slots/thread) ----
    int      off[7];    // running gmem float offset, tile 0 value
    int      sofs[7];   // smem float offset (constant)
    unsigned inb = 0, wok = 0;

    #pragma unroll
    for (int i = 0; i < 7; i++) {
        const int q   = i * TPB + tid;
        const int row = q >> 3;
        const int c4  = q & 7;
        const int rg  = rbase + row;
        const bool v  = (q < N4) && (rg < NROWS_TOTAL);
        inb |= (unsigned)v << i;
        wok |= (unsigned)(v && ((rg & 127) != 0)) << i;
        off[i]  = rg * CHUNK - WARM + c4 * 4;   // tile-0 load == tile-j store form
        sofs[i] = row * PITCH + c4 * 4;
    }

    float4 pf[7];

    // ---- load tile 0 (warm-masked) ----
    #pragma unroll
    for (int i = 0; i < 7; i++)
        pf[i] = ((wok >> i) & 1) ? *reinterpret_cast<const float4*>(x + off[i])
                                 : make_float4(0.f, 0.f, 0.f, 0.f);

    float z0 = 0.f, z1 = 0.f, z2 = 0.f, z3 = 0.f;

    for (int j = 0; j < NT; j++) {
        float* buf = sbuf[j & 1];

        // ---- stage prefetched tile into smem (coalesced STS.128) ----
        #pragma unroll
        for (int i = 0; i < 7; i++)
            if ((inb >> i) & 1)
                *reinterpret_cast<float4*>(buf + sofs[i]) = pf[i];

        // ---- issue next tile's LDGs before the barrier (no smem dep) ----
        if (j + 1 < NT) {
            const unsigned m = (j + 1 <= 7) ? wok : inb;   // uniform branch
            #pragma unroll
            for (int i = 0; i < 7; i++)
                pf[i] = ((m >> i) & 1)
                          ? *reinterpret_cast<const float4*>(x + off[i] + TT)
                          : make_float4(0.f, 0.f, 0.f, 0.f);
        }
        __syncthreads();

        // ---- serial recurrence over own smem row, outputs in place ----
        const bool mainTile = (j >= NT_WARM);
        if (active) {
            float* row = buf + tid * PITCH;
            #pragma unroll
            for (int i = 0; i < 8; i++) {
                const float4 xv = *reinterpret_cast<const float4*>(row + i * 4);
                const float xa[4] = {xv.x, xv.y, xv.z, xv.w};
                float yv[4];
                #pragma unroll
                for (int k = 0; k < 4; k++) {
                    const float xn = xa[k];
                    const float y   = fmaf(b0, xn, z0);
                    const float nz0 = fmaf(na1, y, fmaf(b1, xn, z1));
                    const float nz1 = fmaf(na2, y, fmaf(b2, xn, z2));
                    const float nz2 = fmaf(na3, y, fmaf(b3, xn, z3));
                    const float nz3 = fmaf(na4, y, b4 * xn);
                    z0 = nz0; z1 = nz1; z2 = nz2; z3 = nz3;
                    yv[k] = y;
                }
                if (mainTile)
                    *reinterpret_cast<float4*>(row + i * 4) =
                        make_float4(yv[0], yv[1], yv[2], yv[3]);
            }
        }
        __syncthreads();

        // ---- cooperative coalesced store: out offset == current off ----
        if (mainTile) {
            #pragma unroll
            for (int i = 0; i < 7; i++)
                if ((inb >> i) & 1)
                    *reinterpret_cast<float4*>(out + off[i]) =
                        *reinterpret_cast<const float4*>(buf + sofs[i]);
        }

        // ---- advance running offsets ----
        #pragma unroll
        for (int i = 0; i < 7; i++) off[i] += TT;
    }
}

extern "C" void kernel_launch(void* const* d_in, const int* in_sizes, int n_in,
                              void* d_out, int out_size)
{
    const float* x  = (const float*)d_in[0];   // (128, 4, 65536)
    const float* bc = (const float*)d_in[1];   // (4, 5)
    const float* ac = (const float*)d_in[2];   // (4, 5)
    float* out = (float*)d_out;

    iir_sr_kernel<<<GRID, TPB>>>(x, bc, ac, out);
}